// round 16
// baseline (speedup 1.0000x reference)
#include <cuda_runtime.h>
#include <cuda_bf16.h>
#include <cstdint>

// Problem constants (fixed shapes per reference)
#define NB   8
#define LQ   2048
#define CC   256
#define MM   8
#define LL   4
#define PP   4
#define DH   32
#define SS   3840
#define ROWS_Q (NB * LQ)     // 16384
#define ROWS_V (NB * SS)     // 30720
#define MLP  (MM * LL * PP)  // 128

__constant__ int c_lens[4]  = {2048, 1024, 512, 256};

// ---------------------------------------------------------------------------
// Scratch (device globals; no allocation allowed)
// ---------------------------------------------------------------------------
__device__ float g_val[ROWS_V * CC];           // value projection (fp32)
__device__ float g_offattn[ROWS_Q * 256];      // [off | attn logits]

__device__ __nv_bfloat16 g_in_h[ROWS_V * CC];  // in_flatten hi/lo
__device__ __nv_bfloat16 g_in_l[ROWS_V * CC];
__device__ __nv_bfloat16 g_q_h[ROWS_Q * CC];   // query hi/lo
__device__ __nv_bfloat16 g_q_l[ROWS_Q * CC];
__device__ __nv_bfloat16 g_mid_h[ROWS_Q * CC]; // mid hi/lo (written by deform)
__device__ __nv_bfloat16 g_mid_l[ROWS_Q * CC];

__device__ __nv_bfloat16 g_wv_h[CC * CC],   g_wv_l[CC * CC];    // W_val^T
__device__ __nv_bfloat16 g_wcat_h[CC * CC], g_wcat_l[CC * CC];  // [W_off|W_attn]^T
__device__ __nv_bfloat16 g_wo_h[CC * CC],   g_wo_l[CC * CC];    // W_out^T
__device__ float g_bcat[256];

// ---------------------------------------------------------------------------
// helpers
// ---------------------------------------------------------------------------
static __device__ __forceinline__ uint32_t smem_u32(const void* p) {
    uint32_t a;
    asm("{ .reg .u64 t; cvta.to.shared.u64 t, %1; cvt.u32.u64 %0, t; }"
        : "=r"(a) : "l"(p));
    return a;
}
static __device__ __forceinline__ uint32_t swz128(uint32_t off) {
    return off ^ ((off >> 3) & 0x70);
}
static __device__ __forceinline__ uint32_t pack_hi(float a, float b,
                                                   float& la, float& lb) {
    __nv_bfloat16 ha = __float2bfloat16(a);
    __nv_bfloat16 hb = __float2bfloat16(b);
    la = a - __bfloat162float(ha);
    lb = b - __bfloat162float(hb);
    return (uint32_t)__bfloat16_as_ushort(ha) |
           ((uint32_t)__bfloat16_as_ushort(hb) << 16);
}
static __device__ __forceinline__ uint32_t pack_bf(float a, float b) {
    return (uint32_t)__bfloat16_as_ushort(__float2bfloat16(a)) |
           ((uint32_t)__bfloat16_as_ushort(__float2bfloat16(b)) << 16);
}

#define LDMX4(r0, r1, r2, r3, addr) \
    asm volatile("ldmatrix.sync.aligned.m8n8.x4.shared.b16 {%0,%1,%2,%3}, [%4];" \
                 : "=r"(r0), "=r"(r1), "=r"(r2), "=r"(r3) : "r"(addr))

#define MMA16816(c, a, b0, b1) \
    asm volatile("mma.sync.aligned.m16n8k16.row.col.f32.bf16.bf16.f32 " \
                 "{%0,%1,%2,%3}, {%4,%5,%6,%7}, {%8,%9}, {%0,%1,%2,%3};" \
                 : "+f"((c)[0]), "+f"((c)[1]), "+f"((c)[2]), "+f"((c)[3]) \
                 : "r"((a)[0]), "r"((a)[1]), "r"((a)[2]), "r"((a)[3]), \
                   "r"(b0), "r"(b1))

#define CP16(dst, src) \
    asm volatile("cp.async.cg.shared.global [%0], [%1], 16;" \
                 :: "r"(dst), "l"(src))
#define CP_COMMIT() asm volatile("cp.async.commit_group;" ::: "memory")
#define CP_WAIT(n)  asm volatile("cp.async.wait_group %0;" :: "n"(n) : "memory")

// ===========================================================================
// Activation fp32 -> bf16 hi/lo conversion.
// ===========================================================================
__global__ void convert_act(const float* __restrict__ src,
                            __nv_bfloat16* __restrict__ hi,
                            __nv_bfloat16* __restrict__ lo, int n4)
{
    int i = blockIdx.x * blockDim.x + threadIdx.x;
    const int stride = gridDim.x * blockDim.x;
    for (; i < n4; i += stride) {
        const float4 v = reinterpret_cast<const float4*>(src)[i];
        float l0, l1f, l2f, l3;
        const uint32_t h01 = pack_hi(v.x, v.y, l0, l1f);
        const uint32_t h23 = pack_hi(v.z, v.w, l2f, l3);
        reinterpret_cast<uint2*>(hi)[i] = make_uint2(h01, h23);
        reinterpret_cast<uint2*>(lo)[i] = make_uint2(pack_bf(l0, l1f),
                                                     pack_bf(l2f, l3));
    }
}

// ===========================================================================
// All weight transpose+convert + bias concat in ONE launch (48 blocks).
// ===========================================================================
__global__ __launch_bounds__(256)
void convert_wts_all(const float* __restrict__ W_val,
                     const float* __restrict__ W_off,
                     const float* __restrict__ W_attn,
                     const float* __restrict__ W_out,
                     __nv_bfloat16* __restrict__ wv_h,  __nv_bfloat16* __restrict__ wv_l,
                     __nv_bfloat16* __restrict__ wc_h,  __nv_bfloat16* __restrict__ wc_l,
                     __nv_bfloat16* __restrict__ wo_h,  __nv_bfloat16* __restrict__ wo_l,
                     const float* __restrict__ b_off,
                     const float* __restrict__ b_attn,
                     float* __restrict__ bcat)
{
    __shared__ float s[64][65];
    const int b = blockIdx.x;
    const int t = threadIdx.x;

    const float* W;
    __nv_bfloat16 *Th, *Tl;
    int N, local;
    if (b < 16)      { W = W_val;  Th = wv_h;            Tl = wv_l;            N = 256; local = b; }
    else if (b < 24) { W = W_off;  Th = wc_h;            Tl = wc_l;            N = 128; local = b - 16; }
    else if (b < 32) { W = W_attn; Th = wc_h + 128 * CC; Tl = wc_l + 128 * CC; N = 128; local = b - 24; }
    else             { W = W_out;  Th = wo_h;            Tl = wo_l;            N = 256; local = b - 32; }
    const int ntiles = N >> 6;
    const int n0 = (local % ntiles) * 64;
    const int k0 = (local / ntiles) * 64;

    if (b == 0) bcat[t] = (t < 128) ? b_off[t] : b_attn[t - 128];

#pragma unroll
    for (int j = 0; j < 16; ++j) {
        const int idx = t + j * 256;
        const int r = idx >> 6, c = idx & 63;
        s[r][c] = W[(size_t)(k0 + r) * N + n0 + c];
    }
    __syncthreads();
#pragma unroll
    for (int j = 0; j < 16; ++j) {
        const int idx = t + j * 256;
        const int r = idx >> 6, c = idx & 63;
        const float v = s[c][r];
        const __nv_bfloat16 h = __float2bfloat16(v);
        const float l = v - __bfloat162float(h);
        Th[(size_t)(n0 + r) * CC + k0 + c] = h;
        Tl[(size_t)(n0 + r) * CC + k0 + c] = __float2bfloat16(l);
    }
}

// ===========================================================================
// GEMM core (mma.sync bf16 hi/lo, fp32 acc), K = Nc = 256 fixed.
// Tile 128x128, 8 warps (2m x 4n of 64x32), K chunks of 64, 2-stage cp.async
// smem double-buffer + 2-deep register fragment pipeline across k-steps.
// ===========================================================================
#define STG_SZ  65536
#define T_AH    0
#define T_AL    16384
#define T_BH    32768
#define T_BL    49152
#define GEMM_SMEM (2 * STG_SZ)

static __device__ __forceinline__ void gemm_core(
    const __nv_bfloat16* __restrict__ Ah, const __nv_bfloat16* __restrict__ Al,
    const __nv_bfloat16* __restrict__ Bh, const __nv_bfloat16* __restrict__ Bl,
    const float* __restrict__ bias, float* __restrict__ Cmat,
    int r0, int c0, uint32_t sb)
{
    const int K = 256, Nc = 256;
    const int tid = threadIdx.x;
    const int lane = tid & 31, wid = tid >> 5;
    const int wm = (wid >> 2) * 64;
    const int wn = (wid & 3) * 32;

    float acc[4][4][4];
#pragma unroll
    for (int mt = 0; mt < 4; ++mt)
#pragma unroll
        for (int j = 0; j < 4; ++j)
#pragma unroll
            for (int r = 0; r < 4; ++r) acc[mt][j][r] = 0.f;

    const __nv_bfloat16* srcs[4] = {Ah, Al, Bh, Bl};

    auto load_chunk = [&](int k0, uint32_t stgBase) {
#pragma unroll
        for (int j = 0; j < 16; ++j) {
            const int seg = tid + j * 256;
            const int tile = seg >> 10;
            const int row = (seg & 1023) >> 3;
            const int s8 = seg & 7;
            const int grow = (tile < 2) ? (r0 + row) : (c0 + row);
            const __nv_bfloat16* src =
                srcs[tile] + (size_t)grow * K + k0 + s8 * 8;
            const uint32_t dst =
                stgBase + tile * 16384 + swz128((uint32_t)(row * 128 + s8 * 16));
            CP16(dst, src);
        }
        CP_COMMIT();
    };

    const int matq = lane >> 3, rq = lane & 7;
    uint32_t aRowB[4], bRowB[2];
#pragma unroll
    for (int mt = 0; mt < 4; ++mt)
        aRowB[mt] = (uint32_t)((wm + mt * 16 + (matq & 1) * 8 + rq) * 128 +
                               (matq >> 1) * 16);
#pragma unroll
    for (int nt = 0; nt < 2; ++nt)
        bRowB[nt] = (uint32_t)((wn + nt * 16 + (matq >> 1) * 8 + rq) * 128 +
                               (matq & 1) * 16);

    // 2-deep register fragment pipeline buffers
    uint32_t ah[2][4][4], al[2][4][4], bh[2][2][4], bl[2][2][4];

    auto ldfr = [&](int buf, int ks, uint32_t stg) {
#pragma unroll
        for (int mt = 0; mt < 4; ++mt) {
            const uint32_t off = swz128(aRowB[mt] + (uint32_t)(ks * 32));
            LDMX4(ah[buf][mt][0], ah[buf][mt][1], ah[buf][mt][2], ah[buf][mt][3],
                  stg + T_AH + off);
            LDMX4(al[buf][mt][0], al[buf][mt][1], al[buf][mt][2], al[buf][mt][3],
                  stg + T_AL + off);
        }
#pragma unroll
        for (int nt = 0; nt < 2; ++nt) {
            const uint32_t off = swz128(bRowB[nt] + (uint32_t)(ks * 32));
            LDMX4(bh[buf][nt][0], bh[buf][nt][1], bh[buf][nt][2], bh[buf][nt][3],
                  stg + T_BH + off);
            LDMX4(bl[buf][nt][0], bl[buf][nt][1], bl[buf][nt][2], bl[buf][nt][3],
                  stg + T_BL + off);
        }
    };

    const int nch = K >> 6;   // 4
    load_chunk(0, sb);

#pragma unroll 1
    for (int ch = 0; ch < nch; ++ch) {
        const uint32_t stg = sb + (uint32_t)(ch & 1) * STG_SZ;
        if (ch + 1 < nch) {
            load_chunk((ch + 1) << 6, sb + (uint32_t)((ch + 1) & 1) * STG_SZ);
            CP_WAIT(1);
        } else {
            CP_WAIT(0);
        }
        __syncthreads();

        ldfr(0, 0, stg);
#pragma unroll
        for (int ks = 0; ks < 4; ++ks) {
            const int cur = ks & 1;
            if (ks < 3) ldfr(cur ^ 1, ks + 1, stg);
#pragma unroll
            for (int mt = 0; mt < 4; ++mt) {
#pragma unroll
                for (int nt = 0; nt < 2; ++nt) {
#pragma unroll
                    for (int h = 0; h < 2; ++h) {
                        const int j = nt * 2 + h;
                        MMA16816(acc[mt][j], ah[cur][mt],
                                 bh[cur][nt][2 * h], bh[cur][nt][2 * h + 1]);
                        MMA16816(acc[mt][j], ah[cur][mt],
                                 bl[cur][nt][2 * h], bl[cur][nt][2 * h + 1]);
                        MMA16816(acc[mt][j], al[cur][mt],
                                 bh[cur][nt][2 * h], bh[cur][nt][2 * h + 1]);
                    }
                }
            }
        }
        __syncthreads();
    }

    const int rbase = r0 + wm + (lane >> 2);
    const int cbase = c0 + wn + (lane & 3) * 2;
#pragma unroll
    for (int j = 0; j < 4; ++j) {
        const int col = cbase + j * 8;
        const float bx = __ldg(&bias[col]);
        const float by = __ldg(&bias[col + 1]);
#pragma unroll
        for (int mt = 0; mt < 4; ++mt) {
            const int row = rbase + mt * 16;
            float2 v0 = make_float2(acc[mt][j][0] + bx, acc[mt][j][1] + by);
            float2 v1 = make_float2(acc[mt][j][2] + bx, acc[mt][j][3] + by);
            *reinterpret_cast<float2*>(&Cmat[(size_t)row * Nc + col]) = v0;
            *reinterpret_cast<float2*>(&Cmat[(size_t)(row + 8) * Nc + col]) = v1;
        }
    }
}

// Merged value + offattn GEMM: blockIdx.y in [0,240) -> value rows,
// [240,368) -> offattn rows.
__global__ __launch_bounds__(256, 1)
void gemm_dual(const __nv_bfloat16* __restrict__ A1h, const __nv_bfloat16* __restrict__ A1l,
               const __nv_bfloat16* __restrict__ B1h, const __nv_bfloat16* __restrict__ B1l,
               const float* __restrict__ bias1, float* __restrict__ C1,
               const __nv_bfloat16* __restrict__ A2h, const __nv_bfloat16* __restrict__ A2l,
               const __nv_bfloat16* __restrict__ B2h, const __nv_bfloat16* __restrict__ B2l,
               const float* __restrict__ bias2, float* __restrict__ C2)
{
    extern __shared__ char smem[];
    const uint32_t sb = smem_u32(smem);
    const int by = blockIdx.y;
    const bool first = (by < 240);
    const __nv_bfloat16* Ah = first ? A1h : A2h;
    const __nv_bfloat16* Al = first ? A1l : A2l;
    const __nv_bfloat16* Bh = first ? B1h : B2h;
    const __nv_bfloat16* Bl = first ? B1l : B2l;
    const float* bias = first ? bias1 : bias2;
    float* C = first ? C1 : C2;
    const int r0 = (first ? by : (by - 240)) * 128;
    gemm_core(Ah, Al, Bh, Bl, bias, C, r0, blockIdx.x * 128, sb);
}

__global__ __launch_bounds__(256, 1)
void gemm_single(const __nv_bfloat16* __restrict__ Ah, const __nv_bfloat16* __restrict__ Al,
                 const __nv_bfloat16* __restrict__ Bh, const __nv_bfloat16* __restrict__ Bl,
                 const float* __restrict__ bias, float* __restrict__ Cmat)
{
    extern __shared__ char smem[];
    const uint32_t sb = smem_u32(smem);
    gemm_core(Ah, Al, Bh, Bl, bias, Cmat,
              blockIdx.y * 128, blockIdx.x * 128, sb);
}

// ===========================================================================
// Fused softmax + loc + deformable sampling + mid bf16-split epilogue.
// ===========================================================================
__global__ __launch_bounds__(256)
void deform_fused(const float* __restrict__ val,
                  const float* __restrict__ offattn,
                  const float* __restrict__ refpts,
                  float* __restrict__ loc_out,
                  float* __restrict__ attn_out,
                  __nv_bfloat16* __restrict__ mid_h,
                  __nv_bfloat16* __restrict__ mid_l)
{
    const int wid = threadIdx.x >> 5;
    const int lane = threadIdx.x & 31;
    const long long gw = (long long)blockIdx.x * 8 + wid;
    const int m = (int)(gw & 7);
    const int row = (int)(gw >> 3);
    const int n = row >> 11;
    const int sg = lane >> 3;       // sample slot 0..3
    const int cg = lane & 7;        // float4 channel group

    // --- softmax over 16 logits + loc ---
    const int oroW = row * 256 + m * 16;
    float logit[4], offv[4];
#pragma unroll
    for (int g = 0; g < 4; ++g) {
        const int i = g * 4 + sg;
        offv[g]  = __ldg(&offattn[oroW + i]);
        logit[g] = __ldg(&offattn[oroW + 128 + i]);
    }
    float mx = fmaxf(fmaxf(logit[0], logit[1]), fmaxf(logit[2], logit[3]));
    mx = fmaxf(mx, __shfl_xor_sync(0xffffffffu, mx, 8));
    mx = fmaxf(mx, __shfl_xor_sync(0xffffffffu, mx, 16));
    float e[4], s = 0.f;
#pragma unroll
    for (int g = 0; g < 4; ++g) { e[g] = __expf(logit[g] - mx); s += e[g]; }
    s += __shfl_xor_sync(0xffffffffu, s, 8);
    s += __shfl_xor_sync(0xffffffffu, s, 16);

    float aw[4], lc[4];
#pragma unroll
    for (int g = 0; g < 4; ++g) {
        aw[g] = e[g] / s;
        lc[g] = __ldg(&refpts[row * LL + g]) + offv[g] / (float)c_lens[g];
    }
    if (cg == 0) {
        const int ob = row * MLP + m * 16;
#pragma unroll
        for (int g = 0; g < 4; ++g) {
            attn_out[ob + g * 4 + sg] = aw[g];
            loc_out[ob + g * 4 + sg]  = lc[g];
        }
    }

    // --- sampling ---
    const float4* vb = reinterpret_cast<const float4*>(
        val + ((size_t)n * SS) * CC + m * DH) + cg;

    const int startl[4] = {0, 2048, 3072, 3584};
    float4 acc = make_float4(0.f, 0.f, 0.f, 0.f);
#pragma unroll
    for (int g = 0; g < 4; ++g) {           // level == g
        const int T = c_lens[g];
        const int st = startl[g];
        const float pos = lc[g] * (float)T - 0.5f;
        const float x0f = floorf(pos);
        const float fr = pos - x0f;
        const int x0 = (int)x0f;

        const float w0 = (x0 >= 0 && x0 < T) ? (1.f - fr) * aw[g] : 0.f;
        const float w1 = (x0 + 1 >= 0 && x0 + 1 < T) ? fr * aw[g] : 0.f;
        const int i0 = min(max(x0, 0), T - 1);
        const int i1 = min(max(x0 + 1, 0), T - 1);
        if (w0 != 0.f) {
            const float4 v = vb[(size_t)(st + i0) * (CC / 4)];
            acc.x += w0 * v.x; acc.y += w0 * v.y;
            acc.z += w0 * v.z; acc.w += w0 * v.w;
        }
        if (w1 != 0.f) {
            const float4 v = vb[(size_t)(st + i1) * (CC / 4)];
            acc.x += w1 * v.x; acc.y += w1 * v.y;
            acc.z += w1 * v.z; acc.w += w1 * v.w;
        }
    }
#pragma unroll
    for (int o = 8; o <= 16; o <<= 1) {
        acc.x += __shfl_xor_sync(0xffffffffu, acc.x, o);
        acc.y += __shfl_xor_sync(0xffffffffu, acc.y, o);
        acc.z += __shfl_xor_sync(0xffffffffu, acc.z, o);
        acc.w += __shfl_xor_sync(0xffffffffu, acc.w, o);
    }
    if (sg == 0) {
        float l0, l1, l2, l3;
        const uint32_t h01 = pack_hi(acc.x, acc.y, l0, l1);
        const uint32_t h23 = pack_hi(acc.z, acc.w, l2, l3);
        const size_t base = (size_t)row * CC + m * DH + cg * 4;
        *reinterpret_cast<uint2*>(&mid_h[base]) = make_uint2(h01, h23);
        *reinterpret_cast<uint2*>(&mid_l[base]) =
            make_uint2(pack_bf(l0, l1), pack_bf(l2, l3));
    }
}

// ---------------------------------------------------------------------------
extern "C" void kernel_launch(void* const* d_in, const int* in_sizes, int n_in,
                              void* d_out, int out_size)
{
    const float* query   = (const float*)d_in[0];
    const float* refpts  = (const float*)d_in[1];
    const float* in_flat = (const float*)d_in[2];
    const float* W_off   = (const float*)d_in[5];
    const float* b_off   = (const float*)d_in[6];
    const float* W_attn  = (const float*)d_in[7];
    const float* b_attn  = (const float*)d_in[8];
    const float* W_val   = (const float*)d_in[9];
    const float* b_val   = (const float*)d_in[10];
    const float* W_out   = (const float*)d_in[11];
    const float* b_out   = (const float*)d_in[12];

    float* out_main = (float*)d_out;
    float* out_loc  = out_main + (size_t)ROWS_Q * CC;
    float* out_attn = out_loc  + (size_t)ROWS_Q * MLP;

    float *d_val, *d_offattn, *d_bcat;
    __nv_bfloat16 *d_in_h, *d_in_l, *d_q_h, *d_q_l, *d_mid_h, *d_mid_l;
    __nv_bfloat16 *d_wv_h, *d_wv_l, *d_wcat_h, *d_wcat_l, *d_wo_h, *d_wo_l;
    cudaGetSymbolAddress((void**)&d_val,     g_val);
    cudaGetSymbolAddress((void**)&d_offattn, g_offattn);
    cudaGetSymbolAddress((void**)&d_bcat,    g_bcat);
    cudaGetSymbolAddress((void**)&d_in_h,    g_in_h);
    cudaGetSymbolAddress((void**)&d_in_l,    g_in_l);
    cudaGetSymbolAddress((void**)&d_q_h,     g_q_h);
    cudaGetSymbolAddress((void**)&d_q_l,     g_q_l);
    cudaGetSymbolAddress((void**)&d_mid_h,   g_mid_h);
    cudaGetSymbolAddress((void**)&d_mid_l,   g_mid_l);
    cudaGetSymbolAddress((void**)&d_wv_h,    g_wv_h);
    cudaGetSymbolAddress((void**)&d_wv_l,    g_wv_l);
    cudaGetSymbolAddress((void**)&d_wcat_h,  g_wcat_h);
    cudaGetSymbolAddress((void**)&d_wcat_l,  g_wcat_l);
    cudaGetSymbolAddress((void**)&d_wo_h,    g_wo_h);
    cudaGetSymbolAddress((void**)&d_wo_l,    g_wo_l);

    static bool init_done = false;
    static cudaStream_t s2;
    static cudaEvent_t evFork, evIn;
    if (!init_done) {
        cudaFuncSetAttribute(gemm_dual,
                             cudaFuncAttributeMaxDynamicSharedMemorySize,
                             GEMM_SMEM);
        cudaFuncSetAttribute(gemm_single,
                             cudaFuncAttributeMaxDynamicSharedMemorySize,
                             GEMM_SMEM);
        cudaStreamCreateWithFlags(&s2, cudaStreamNonBlocking);
        cudaEventCreateWithFlags(&evFork, cudaEventDisableTiming);
        cudaEventCreateWithFlags(&evIn,   cudaEventDisableTiming);
        init_done = true;
    }

    // ---- fork: side stream converts in_flatten while default does the rest
    cudaEventRecord(evFork, 0);
    cudaStreamWaitEvent(s2, evFork, 0);
    convert_act<<<1536, 256, 0, s2>>>(in_flat, d_in_h, d_in_l, ROWS_V * CC / 4);
    cudaEventRecord(evIn, s2);

    convert_wts_all<<<48, 256>>>(W_val, W_off, W_attn, W_out,
                                 d_wv_h, d_wv_l, d_wcat_h, d_wcat_l,
                                 d_wo_h, d_wo_l, b_off, b_attn, d_bcat);
    convert_act<<<512, 256>>>(query, d_q_h, d_q_l, ROWS_Q * CC / 4);

    // ---- join, then merged value+offattn GEMM (736 CTAs, ~5 full waves)
    cudaStreamWaitEvent(0, evIn, 0);
    gemm_dual<<<dim3(2, 368), 256, GEMM_SMEM>>>(
        d_in_h, d_in_l, d_wv_h, d_wv_l, b_val, d_val,
        d_q_h,  d_q_l,  d_wcat_h, d_wcat_l, d_bcat, d_offattn);

    // ---- fused softmax + loc + sampling + mid bf16 split
    deform_fused<<<ROWS_Q, 256>>>(d_val, d_offattn, refpts,
                                  out_loc, out_attn, d_mid_h, d_mid_l);

    // ---- output projection -> out_main
    gemm_single<<<dim3(2, 128), 256, GEMM_SMEM>>>(
        d_mid_h, d_mid_l, d_wo_h, d_wo_l, b_out, out_main);
}